// round 1
// baseline (speedup 1.0000x reference)
#include <cuda_runtime.h>
#include <math.h>

// Problem constants
#define T_DIM 64
#define B_DIM 512
#define D_DIM 1536
#define H_DIM 1024
#define M_DIM (T_DIM * B_DIM)   // 32768 rows
#define DISCOUNT 0.997f
#define LAM 0.95f

// Allocation-free scratch: ping-pong activation buffers + value vector.
__device__ float g_buf0[(size_t)M_DIM * H_DIM];
__device__ float g_buf1[(size_t)M_DIM * H_DIM];
__device__ float g_value[M_DIM];

// ---------------------------------------------------------------------------
// GEMM: C[M,1024] = act(A[M,K] @ W[K,1024] + bias), act = SiLU if do_silu.
// 128x128 block tile, BK=8, 256 threads, 8x8 per-thread micro-tile,
// double-buffered shared memory (one __syncthreads per k-tile).
// M=32768, N=1024 fixed; K in {1536, 1024}.
// ---------------------------------------------------------------------------
__global__ void __launch_bounds__(256, 2)
gemm_bias_silu(const float* __restrict__ A, const float* __restrict__ W,
               const float* __restrict__ bias, float* __restrict__ C,
               int K, int do_silu)
{
    __shared__ float As[2][8][128];   // transposed A tile: As[k][m]
    __shared__ float Bs[2][8][128];   // B tile: Bs[k][n]

    const int tid = threadIdx.x;
    const int tx = tid & 15;          // 16 thread-cols
    const int ty = tid >> 4;          // 16 thread-rows
    const int row0 = blockIdx.y * 128;
    const int col0 = blockIdx.x * 128;

    // Global-load assignments: each thread loads one float4 of A and one of W per k-tile.
    const int a_row = tid >> 1;            // 0..127
    const int a_col = (tid & 1) << 2;      // 0 or 4
    const int b_row = tid >> 5;            // 0..7
    const int b_col = (tid & 31) << 2;     // 0..124

    const float* Aptr = A + (size_t)(row0 + a_row) * K + a_col;
    const float* Wptr = W + (size_t)b_row * H_DIM + col0 + b_col;

    // Stage 0 load
    float4 av = *(const float4*)(Aptr);
    float4 bv = *(const float4*)(Wptr);
    As[0][a_col + 0][a_row] = av.x;
    As[0][a_col + 1][a_row] = av.y;
    As[0][a_col + 2][a_row] = av.z;
    As[0][a_col + 3][a_row] = av.w;
    *(float4*)&Bs[0][b_row][b_col] = bv;
    __syncthreads();

    float acc[8][8];
    #pragma unroll
    for (int i = 0; i < 8; i++)
        #pragma unroll
        for (int j = 0; j < 8; j++) acc[i][j] = 0.0f;

    const int nk = K >> 3;
    int cur = 0;
    for (int kt = 0; kt < nk; kt++) {
        const bool has_next = (kt + 1 < nk);
        if (has_next) {
            av = *(const float4*)(Aptr + (kt + 1) * 8);
            bv = *(const float4*)(Wptr + (size_t)(kt + 1) * 8 * H_DIM);
        }
        #pragma unroll
        for (int kk = 0; kk < 8; kk++) {
            float a[8], b[8];
            *(float4*)(a)     = *(const float4*)&As[cur][kk][ty * 8];
            *(float4*)(a + 4) = *(const float4*)&As[cur][kk][ty * 8 + 4];
            *(float4*)(b)     = *(const float4*)&Bs[cur][kk][tx * 8];
            *(float4*)(b + 4) = *(const float4*)&Bs[cur][kk][tx * 8 + 4];
            #pragma unroll
            for (int i = 0; i < 8; i++)
                #pragma unroll
                for (int j = 0; j < 8; j++)
                    acc[i][j] = fmaf(a[i], b[j], acc[i][j]);
        }
        if (has_next) {
            const int nxt = cur ^ 1;
            As[nxt][a_col + 0][a_row] = av.x;
            As[nxt][a_col + 1][a_row] = av.y;
            As[nxt][a_col + 2][a_row] = av.z;
            As[nxt][a_col + 3][a_row] = av.w;
            *(float4*)&Bs[nxt][b_row][b_col] = bv;
            __syncthreads();
            cur = nxt;
        }
    }

    // Epilogue: bias + SiLU, vectorized stores.
    const int ccol = col0 + tx * 8;
    #pragma unroll
    for (int i = 0; i < 8; i++) {
        const size_t rbase = (size_t)(row0 + ty * 8 + i) * H_DIM + ccol;
        float v[8];
        #pragma unroll
        for (int j = 0; j < 8; j++) {
            float x = acc[i][j] + bias[ccol + j];
            if (do_silu) x = x / (1.0f + expf(-x));
            v[j] = x;
        }
        *(float4*)&C[rbase]     = make_float4(v[0], v[1], v[2], v[3]);
        *(float4*)&C[rbase + 4] = make_float4(v[4], v[5], v[6], v[7]);
    }
}

// ---------------------------------------------------------------------------
// value[m] = h[m,:] . Wo + bo   (one warp per row)
// ---------------------------------------------------------------------------
__global__ void __launch_bounds__(256)
value_kernel(const float* __restrict__ h, const float* __restrict__ Wo,
             const float* __restrict__ bo, float* __restrict__ value)
{
    const int warp = (blockIdx.x * blockDim.x + threadIdx.x) >> 5;
    const int lane = threadIdx.x & 31;
    if (warp >= M_DIM) return;
    const float4* row = (const float4*)(h + (size_t)warp * H_DIM);
    const float4* w4  = (const float4*)Wo;
    float s = 0.0f;
    #pragma unroll
    for (int i = 0; i < 8; i++) {
        const float4 hv = row[lane + 32 * i];
        const float4 wv = w4[lane + 32 * i];
        s += hv.x * wv.x + hv.y * wv.y + hv.z * wv.z + hv.w * wv.w;
    }
    #pragma unroll
    for (int o = 16; o > 0; o >>= 1) s += __shfl_down_sync(0xffffffffu, s, o);
    if (lane == 0) value[warp] = s + bo[0];
}

// ---------------------------------------------------------------------------
// GAE lambda-return reverse scan. One thread per batch column (512 threads).
// out[0 .. 63*512)      = ret
// out[63*512 .. 2*63*512) = baseline (= value[:-1])
// ---------------------------------------------------------------------------
__global__ void __launch_bounds__(256)
scan_kernel(const float* __restrict__ reward, const float* __restrict__ cont,
            const float* __restrict__ value, float* __restrict__ out)
{
    const int b = blockIdx.x * blockDim.x + threadIdx.x;
    if (b >= B_DIM) return;
    float adv = 0.0f;
    float v_next = value[(T_DIM - 1) * B_DIM + b];
    for (int t = T_DIM - 2; t >= 0; t--) {
        const float v0   = value[t * B_DIM + b];
        const float disc = cont[(t + 1) * B_DIM + b] * DISCOUNT;
        const float dl   = disc * LAM;
        const float delta = reward[t * B_DIM + b] + disc * v_next - v0;
        adv = delta + dl * adv;
        out[t * B_DIM + b] = adv + v0;                               // ret
        out[(T_DIM - 1) * B_DIM + t * B_DIM + b] = v0;               // baseline
        v_next = v0;
    }
}

// ---------------------------------------------------------------------------
extern "C" void kernel_launch(void* const* d_in, const int* in_sizes, int n_in,
                              void* d_out, int out_size)
{
    const float* feat   = (const float*)d_in[0];
    const float* reward = (const float*)d_in[1];
    const float* cont   = (const float*)d_in[2];
    const float* W0 = (const float*)d_in[3];
    const float* b0 = (const float*)d_in[4];
    const float* W1 = (const float*)d_in[5];
    const float* b1 = (const float*)d_in[6];
    const float* W2 = (const float*)d_in[7];
    const float* b2 = (const float*)d_in[8];
    const float* W3 = (const float*)d_in[9];
    const float* b3 = (const float*)d_in[10];
    const float* Wo = (const float*)d_in[11];
    const float* bo = (const float*)d_in[12];
    float* out = (float*)d_out;

    float *buf0, *buf1, *val;
    cudaGetSymbolAddress((void**)&buf0, g_buf0);
    cudaGetSymbolAddress((void**)&buf1, g_buf1);
    cudaGetSymbolAddress((void**)&val,  g_value);

    dim3 block(256);
    dim3 grid(H_DIM / 128, M_DIM / 128);   // (8, 256)

    gemm_bias_silu<<<grid, block>>>(feat, W0, b0, buf0, D_DIM, 1);
    gemm_bias_silu<<<grid, block>>>(buf0, W1, b1, buf1, H_DIM, 1);
    gemm_bias_silu<<<grid, block>>>(buf1, W2, b2, buf0, H_DIM, 1);
    gemm_bias_silu<<<grid, block>>>(buf0, W3, b3, buf1, H_DIM, 1);

    value_kernel<<<M_DIM / 8, 256>>>(buf1, Wo, bo, val);
    scan_kernel<<<2, 256>>>(reward, cont, val, out);
}

// round 3
// speedup vs baseline: 2.1403x; 2.1403x over previous
#include <cuda_runtime.h>
#include <cuda_bf16.h>
#include <cstdint>
#include <math.h>

#define T_DIM 64
#define B_DIM 512
#define D_DIM 1536
#define H_DIM 1024
#define M_DIM (T_DIM * B_DIM)   // 32768
#define DISCOUNT 0.997f
#define LAM 0.95f

// Scratch (allocation-free)
__device__ float g_buf0[(size_t)M_DIM * H_DIM];
__device__ float g_buf1[(size_t)M_DIM * H_DIM];
__device__ float g_partial[32 * (size_t)M_DIM];   // per-(ntile,warp-col) value partials

// ---------------------------------------------------------------------------
// smem: 4 tiles per stage (A_hi, A_mid, B_hi, B_mid), each [128][40] bf16.
// Stride 40 halves (80 B) -> all fragment LDS.32 are bank-conflict-free.
// ---------------------------------------------------------------------------
#define STRIDE_H 40
#define TILE_BYTES (128 * STRIDE_H * 2)      // 10240
#define STAGE_BYTES (4 * TILE_BYTES)         // 40960
#define SMEM_BYTES (2 * STAGE_BYTES)         // 81920

__device__ __forceinline__ float bf16_rn(float x) {
    return __bfloat162float(__float2bfloat16(x));
}
// pack two floats -> bf16x2 (lo = first elem, hi = second elem)
__device__ __forceinline__ uint32_t packbf(float lo, float hi) {
    uint32_t r;
    asm("cvt.rn.bf16x2.f32 %0, %1, %2;" : "=r"(r) : "f"(hi), "f"(lo));
    return r;
}

__device__ __forceinline__ void mma16816(float* d, const uint32_t* a, const uint32_t* b) {
    asm volatile(
        "mma.sync.aligned.m16n8k16.row.col.f32.bf16.bf16.f32 "
        "{%0,%1,%2,%3}, {%4,%5,%6,%7}, {%8,%9}, {%0,%1,%2,%3};"
        : "+f"(d[0]), "+f"(d[1]), "+f"(d[2]), "+f"(d[3])
        : "r"(a[0]), "r"(a[1]), "r"(a[2]), "r"(a[3]), "r"(b[0]), "r"(b[1]));
}

__device__ __forceinline__ float silu(float x) { return x / (1.0f + expf(-x)); }

// ---------------------------------------------------------------------------
// C[M,1024] = silu(A[M,K] @ W[K,1024] + bias)  via 3xBF16 split mma.sync.
// mode 0: write activations. mode 1: fused value head -> g_partial.
// ---------------------------------------------------------------------------
__global__ void __launch_bounds__(256, 1)
gemm_hmma(const float* __restrict__ A, const float* __restrict__ W,
          const float* __restrict__ bias, float* __restrict__ C,
          const float* __restrict__ Wo, float* __restrict__ partial,
          int K, int mode)
{
    extern __shared__ char smem[];
    const int tid  = threadIdx.x;
    const int wid  = tid >> 5;
    const int lane = tid & 31;
    const int row0 = blockIdx.y * 128;
    const int col0 = blockIdx.x * 128;

    // warp layout: 2 (m) x 4 (n); warp tile 64 x 32
    const int wm = wid & 1;
    const int wn = wid >> 1;

    // global load mappings
    const int m_a  = tid >> 3;            // A row 0..31 (+32*it)
    const int kc_a = (tid & 7) * 4;       // A k-float 0..28
    const int n_b  = tid & 127;           // B col
    const int kg_b = (tid >> 7) * 4;      // B k base {0,4} (+8*it, +j)

    const float* Aptr = A + (size_t)(row0 + m_a) * K + kc_a;
    const float* Wptr = W + (size_t)kg_b * H_DIM + col0 + n_b;

    float acc[4][4][4];
    #pragma unroll
    for (int i = 0; i < 4; i++)
        #pragma unroll
        for (int j = 0; j < 4; j++)
            #pragma unroll
            for (int c = 0; c < 4; c++) acc[i][j][c] = 0.0f;

    const int nk = K >> 5;
    float4 av[4];
    float  bw[4][4];

    // ---- load chunk 0 ----
    #pragma unroll
    for (int it = 0; it < 4; it++)
        av[it] = *(const float4*)(Aptr + (size_t)(32 * it) * K);
    #pragma unroll
    for (int it = 0; it < 4; it++)
        #pragma unroll
        for (int j = 0; j < 4; j++)
            bw[it][j] = Wptr[(size_t)(8 * it + j) * H_DIM];

    // ---- STS helper (macro-ish via lambda) ----
    auto do_sts = [&](int buf) {
        uint32_t* Ah = (uint32_t*)(smem + buf * STAGE_BYTES);
        uint32_t* Am = (uint32_t*)(smem + buf * STAGE_BYTES + TILE_BYTES);
        uint32_t* Bh = (uint32_t*)(smem + buf * STAGE_BYTES + 2 * TILE_BYTES);
        uint32_t* Bm = (uint32_t*)(smem + buf * STAGE_BYTES + 3 * TILE_BYTES);
        #pragma unroll
        for (int it = 0; it < 4; it++) {
            const int idx = ((m_a + 32 * it) * STRIDE_H + kc_a) >> 1;  // uint32 units
            float hx = bf16_rn(av[it].x), hy = bf16_rn(av[it].y);
            float hz = bf16_rn(av[it].z), hw = bf16_rn(av[it].w);
            Ah[idx]     = packbf(hx, hy);
            Ah[idx + 1] = packbf(hz, hw);
            Am[idx]     = packbf(av[it].x - hx, av[it].y - hy);
            Am[idx + 1] = packbf(av[it].z - hz, av[it].w - hw);
        }
        #pragma unroll
        for (int it = 0; it < 4; it++) {
            const int idx = (n_b * STRIDE_H + kg_b + 8 * it) >> 1;
            float h0 = bf16_rn(bw[it][0]), h1 = bf16_rn(bw[it][1]);
            float h2 = bf16_rn(bw[it][2]), h3 = bf16_rn(bw[it][3]);
            Bh[idx]     = packbf(h0, h1);
            Bh[idx + 1] = packbf(h2, h3);
            Bm[idx]     = packbf(bw[it][0] - h0, bw[it][1] - h1);
            Bm[idx + 1] = packbf(bw[it][2] - h2, bw[it][3] - h3);
        }
    };

    do_sts(0);
    __syncthreads();

    for (int kt = 0; kt < nk; kt++) {
        const int buf = kt & 1;
        // prefetch next chunk into registers
        if (kt + 1 < nk) {
            #pragma unroll
            for (int it = 0; it < 4; it++)
                av[it] = *(const float4*)(Aptr + (size_t)(32 * it) * K + (kt + 1) * 32);
            #pragma unroll
            for (int it = 0; it < 4; it++)
                #pragma unroll
                for (int j = 0; j < 4; j++)
                    bw[it][j] = Wptr[(size_t)((kt + 1) * 32 + 8 * it + j) * H_DIM];
        }

        // compute on buf
        const uint32_t* Ah = (const uint32_t*)(smem + buf * STAGE_BYTES);
        const uint32_t* Am = (const uint32_t*)(smem + buf * STAGE_BYTES + TILE_BYTES);
        const uint32_t* Bh = (const uint32_t*)(smem + buf * STAGE_BYTES + 2 * TILE_BYTES);
        const uint32_t* Bm = (const uint32_t*)(smem + buf * STAGE_BYTES + 3 * TILE_BYTES);

        #pragma unroll
        for (int ks = 0; ks < 2; ks++) {
            uint32_t RA[4][2][4];
            uint32_t RB[4][2][2];
            const int kcol = ks * 8 + (lane & 3);          // uint32 units within row
            #pragma unroll
            for (int mi = 0; mi < 4; mi++) {
                const int r = wm * 64 + mi * 16 + (lane >> 2);
                const int i00 = r * (STRIDE_H / 2) + kcol;
                const int i10 = (r + 8) * (STRIDE_H / 2) + kcol;
                RA[mi][0][0] = Ah[i00]; RA[mi][0][1] = Ah[i10];
                RA[mi][0][2] = Ah[i00 + 4]; RA[mi][0][3] = Ah[i10 + 4];
                RA[mi][1][0] = Am[i00]; RA[mi][1][1] = Am[i10];
                RA[mi][1][2] = Am[i00 + 4]; RA[mi][1][3] = Am[i10 + 4];
            }
            #pragma unroll
            for (int ni = 0; ni < 4; ni++) {
                const int n = wn * 32 + ni * 8 + (lane >> 2);
                const int i0 = n * (STRIDE_H / 2) + kcol;
                RB[ni][0][0] = Bh[i0]; RB[ni][0][1] = Bh[i0 + 4];
                RB[ni][1][0] = Bm[i0]; RB[ni][1][1] = Bm[i0 + 4];
            }
            #pragma unroll
            for (int mi = 0; mi < 4; mi++)
                #pragma unroll
                for (int ni = 0; ni < 4; ni++) {
                    mma16816(acc[mi][ni], RA[mi][0], RB[ni][0]);  // hi*hi
                    mma16816(acc[mi][ni], RA[mi][0], RB[ni][1]);  // hi*mid
                    mma16816(acc[mi][ni], RA[mi][1], RB[ni][0]);  // mid*hi
                }
        }

        if (kt + 1 < nk) {
            do_sts(buf ^ 1);
            __syncthreads();
        }
    }

    // ---- epilogue ----
    if (mode == 0) {
        #pragma unroll
        for (int mi = 0; mi < 4; mi++) {
            const int grow = row0 + wm * 64 + mi * 16 + (lane >> 2);
            #pragma unroll
            for (int ni = 0; ni < 4; ni++) {
                const int gcol = col0 + wn * 32 + ni * 8 + (lane & 3) * 2;
                const float bi0 = bias[gcol], bi1 = bias[gcol + 1];
                float2 v0, v1;
                v0.x = silu(acc[mi][ni][0] + bi0);
                v0.y = silu(acc[mi][ni][1] + bi1);
                v1.x = silu(acc[mi][ni][2] + bi0);
                v1.y = silu(acc[mi][ni][3] + bi1);
                *(float2*)&C[(size_t)grow * H_DIM + gcol]       = v0;
                *(float2*)&C[(size_t)(grow + 8) * H_DIM + gcol] = v1;
            }
        }
    } else {
        const int p = blockIdx.x * 4 + wn;
        #pragma unroll
        for (int mi = 0; mi < 4; mi++) {
            float s0 = 0.0f, s1 = 0.0f;
            #pragma unroll
            for (int ni = 0; ni < 4; ni++) {
                const int gcol = col0 + wn * 32 + ni * 8 + (lane & 3) * 2;
                const float bi0 = bias[gcol], bi1 = bias[gcol + 1];
                const float w0 = Wo[gcol], w1 = Wo[gcol + 1];
                s0 += silu(acc[mi][ni][0] + bi0) * w0 + silu(acc[mi][ni][1] + bi1) * w1;
                s1 += silu(acc[mi][ni][2] + bi0) * w0 + silu(acc[mi][ni][3] + bi1) * w1;
            }
            // reduce across the 4 lanes sharing a row (lane&3 varies)
            s0 += __shfl_xor_sync(0xffffffffu, s0, 1);
            s0 += __shfl_xor_sync(0xffffffffu, s0, 2);
            s1 += __shfl_xor_sync(0xffffffffu, s1, 1);
            s1 += __shfl_xor_sync(0xffffffffu, s1, 2);
            if ((lane & 3) == 0) {
                const int r = row0 + wm * 64 + mi * 16 + (lane >> 2);
                partial[(size_t)p * M_DIM + r]     = s0;
                partial[(size_t)p * M_DIM + r + 8] = s1;
            }
        }
    }
}

// ---------------------------------------------------------------------------
// GAE reverse scan; value[m] = sum of 32 partials + bo.
// ---------------------------------------------------------------------------
__global__ void __launch_bounds__(256)
scan_kernel(const float* __restrict__ reward, const float* __restrict__ cont,
            const float* __restrict__ partial, const float* __restrict__ bo,
            float* __restrict__ out)
{
    const int b = blockIdx.x * blockDim.x + threadIdx.x;
    if (b >= B_DIM) return;
    const float bov = bo[0];

    auto val = [&](int m) {
        float s = 0.0f;
        #pragma unroll
        for (int c = 0; c < 32; c++) s += partial[(size_t)c * M_DIM + m];
        return s + bov;
    };

    float adv = 0.0f;
    float v_next = val((T_DIM - 1) * B_DIM + b);
    for (int t = T_DIM - 2; t >= 0; t--) {
        const float v0   = val(t * B_DIM + b);
        const float disc = cont[(t + 1) * B_DIM + b] * DISCOUNT;
        const float dl   = disc * LAM;
        const float delta = reward[t * B_DIM + b] + disc * v_next - v0;
        adv = delta + dl * adv;
        out[t * B_DIM + b] = adv + v0;                       // ret
        out[(T_DIM - 1) * B_DIM + t * B_DIM + b] = v0;       // baseline
        v_next = v0;
    }
}

// ---------------------------------------------------------------------------
extern "C" void kernel_launch(void* const* d_in, const int* in_sizes, int n_in,
                              void* d_out, int out_size)
{
    const float* feat   = (const float*)d_in[0];
    const float* reward = (const float*)d_in[1];
    const float* cont   = (const float*)d_in[2];
    const float* W0 = (const float*)d_in[3];
    const float* b0 = (const float*)d_in[4];
    const float* W1 = (const float*)d_in[5];
    const float* b1 = (const float*)d_in[6];
    const float* W2 = (const float*)d_in[7];
    const float* b2 = (const float*)d_in[8];
    const float* W3 = (const float*)d_in[9];
    const float* b3 = (const float*)d_in[10];
    const float* Wo = (const float*)d_in[11];
    const float* bo = (const float*)d_in[12];
    float* out = (float*)d_out;

    float *buf0, *buf1, *part;
    cudaGetSymbolAddress((void**)&buf0, g_buf0);
    cudaGetSymbolAddress((void**)&buf1, g_buf1);
    cudaGetSymbolAddress((void**)&part, g_partial);

    cudaFuncSetAttribute(gemm_hmma, cudaFuncAttributeMaxDynamicSharedMemorySize, SMEM_BYTES);

    dim3 grid(H_DIM / 128, M_DIM / 128);   // (8, 256)
    gemm_hmma<<<grid, 256, SMEM_BYTES>>>(feat, W0, b0, buf0, nullptr, nullptr, D_DIM, 0);
    gemm_hmma<<<grid, 256, SMEM_BYTES>>>(buf0, W1, b1, buf1, nullptr, nullptr, H_DIM, 0);
    gemm_hmma<<<grid, 256, SMEM_BYTES>>>(buf1, W2, b2, buf0, nullptr, nullptr, H_DIM, 0);
    gemm_hmma<<<grid, 256, SMEM_BYTES>>>(buf0, W3, b3, nullptr, Wo, part, H_DIM, 1);
    scan_kernel<<<2, 256>>>(reward, cont, part, bo, out);
}